// round 14
// baseline (speedup 1.0000x reference)
#include <cuda_runtime.h>
#include <cuda_fp16.h>
#include <cstdint>

// ---------------- shapes ----------------
#define B_   2048
#define F_   32
#define P_   64
#define E_   64
#define H_   128
#define M_   512      // K of GEMM2
#define D_   1024
#define EPSV 1e-5f

// ---------------- device scratch ----------------
__device__ float g_C0[M_], g_C1[M_], g_v[M_], g_s1[M_], g_c1[M_];
__device__ float g_s2[D_], g_c2[D_];
__device__ float g_p[B_ * M_];
__device__ float g_q[B_ * M_];
// W2^T fp16: [dc(16)][d(64)][k(512) ^ ((d&7)<<3)]  (XOR-swizzled rows of 1KB)
__device__ __half g_Wh[16 * 64 * 512];

// ---------------- SMEM layout (bytes, dynamic) ----------------
#define SM_Q     0        // q_s[4][512] f32 = 8192
#define SM_W     8192     // W tile fp16 64x512 swizzled = 65536
#define SM_Z     73728    // z buf: 256n x 64k fp16 = 32768
#define SM_TOTAL 106496

#define NITEMS 2048       // (dc 16) x (f 32) x (igq 4)

__device__ __forceinline__ uint32_t smem_u32(const void* p) {
    uint32_t a;
    asm("{ .reg .u64 t; cvta.to.shared.u64 t, %1; cvt.u32.u64 %0, t; }" : "=r"(a) : "l"(p));
    return a;
}
__device__ __forceinline__ void ldsm4(uint32_t* r, uint32_t addr) {
    asm volatile("ldmatrix.sync.aligned.m8n8.x4.shared.b16 {%0,%1,%2,%3}, [%4];"
                 : "=r"(r[0]), "=r"(r[1]), "=r"(r[2]), "=r"(r[3]) : "r"(addr));
}
__device__ __forceinline__ void mma16816(float* c, const uint32_t* a,
                                         uint32_t b0, uint32_t b1) {
    asm volatile(
        "mma.sync.aligned.m16n8k16.row.col.f32.f16.f16.f32 "
        "{%0,%1,%2,%3}, {%4,%5,%6,%7}, {%8,%9}, {%0,%1,%2,%3};"
        : "+f"(c[0]), "+f"(c[1]), "+f"(c[2]), "+f"(c[3])
        : "r"(a[0]), "r"(a[1]), "r"(a[2]), "r"(a[3]), "r"(b0), "r"(b1));
}

// ---------------- prep0: fold constants ----------------
__global__ void prep0(const float* __restrict__ We, const float* __restrict__ be,
                      const float* __restrict__ W1,
                      const float* __restrict__ g1, const float* __restrict__ beta1,
                      const float* __restrict__ rm1, const float* __restrict__ rv1,
                      const float* __restrict__ b2, const float* __restrict__ g2,
                      const float* __restrict__ beta2,
                      const float* __restrict__ rm2, const float* __restrict__ rv2) {
    int m = threadIdx.x;  // 512
    float c0 = 0.f, c1 = 0.f, vv = 0.f;
#pragma unroll 8
    for (int e = 0; e < E_; e++) {
        float w = W1[e * M_ + m];
        c0 += We[e] * w;
        c1 += We[E_ + e] * w;
        vv += be[e] * w;
    }
    g_C0[m] = c0;
    g_C1[m] = c1;
    g_v[m]  = vv;
    float s = g1[m] * rsqrtf(rv1[m] + EPSV);
    g_s1[m] = s;
    g_c1[m] = beta1[m] - s * rm1[m];
    for (int d = m; d < D_; d += M_) {
        float s2 = g2[d] * rsqrtf(rv2[d] + EPSV);
        g_s2[d] = s2;
        g_c2[d] = beta2[d] + s2 * (b2[d] - rm2[d]);
    }
}

// ---------------- prep1: build p,q ----------------
__global__ void prep1(const float* __restrict__ h, const float* __restrict__ pos,
                      const float* __restrict__ W1, const float* __restrict__ b1) {
    __shared__ float hs[8][H_];
    __shared__ float ps[8][2];
    int tid = threadIdx.x;
    int b0 = blockIdx.x * 8;
    for (int idx = tid; idx < 8 * H_; idx += 256) {
        int bb = idx >> 7, k = idx & 127;
        hs[bb][k] = h[(b0 + bb) * H_ + k];
    }
    if (tid < 16) ps[tid >> 1][tid & 1] = pos[b0 * 2 + tid];
    __syncthreads();

    int m0 = tid * 2;
    float acc[8][2];
#pragma unroll
    for (int bb = 0; bb < 8; bb++) { acc[bb][0] = 0.f; acc[bb][1] = 0.f; }
#pragma unroll 4
    for (int k = 0; k < H_; k++) {
        float2 w = *(const float2*)&W1[(E_ + k) * M_ + m0];
#pragma unroll
        for (int bb = 0; bb < 8; bb++) {
            float hv = hs[bb][k];
            acc[bb][0] += hv * w.x;
            acc[bb][1] += hv * w.y;
        }
    }
#pragma unroll
    for (int mm = 0; mm < 2; mm++) {
        int m = m0 + mm;
        float C0 = g_C0[m], C1 = g_C1[m], vv = g_v[m];
        float s = g_s1[m], cc = g_c1[m], bb1 = b1[m];
#pragma unroll
        for (int bb = 0; bb < 8; bb++) {
            float u = ps[bb][0] * C0 + ps[bb][1] * C1;
            float a = u + acc[bb][mm] + vv + bb1;
            g_p[(b0 + bb) * M_ + m] = s * a + cc;
            g_q[(b0 + bb) * M_ + m] = s * u;
        }
    }
}

// ---------------- prep2: W2^T -> fp16 swizzled (64-row tiles) ----------------
__global__ void prep2(const float* __restrict__ W2) {
    int dc = blockIdx.x;   // 0..15
    int ks = blockIdx.y;   // 0..7 (k-slab of 64)
    for (int idx = threadIdx.x; idx < 4096; idx += 256) {
        int d = idx & 63;                  // coalesced over d
        int k = ks * 64 + (idx >> 6);
        float w = W2[(size_t)k * D_ + dc * 64 + d];
        int kk = k ^ ((d & 7) << 3);
        g_Wh[dc * 32768 + d * 512 + kk] = __float2half_rn(w);
    }
}

// ---------------- build one il-quarter of the z chunk ----------------
// thread map: bj = tid>>2 (j row), qt = tid&3 (16-k quarter).
__device__ __forceinline__ void build_quarter(char* zbuf, const float* q_s,
                                              const float4* pv, int kc, int il,
                                              int bj, int qt) {
    const float4* qq = (const float4*)(q_s + il * 512 + kc * 64 + qt * 16);
    float4 q0 = qq[0], q1 = qq[1], q2 = qq[2], q3 = qq[3];
    float4 p0 = pv[0], p1 = pv[1], p2 = pv[2], p3 = pv[3];
    __half2 h0 = __floats2half2_rn(fmaxf(p0.x - q0.x, 0.f), fmaxf(p0.y - q0.y, 0.f));
    __half2 h1 = __floats2half2_rn(fmaxf(p0.z - q0.z, 0.f), fmaxf(p0.w - q0.w, 0.f));
    __half2 h2 = __floats2half2_rn(fmaxf(p1.x - q1.x, 0.f), fmaxf(p1.y - q1.y, 0.f));
    __half2 h3 = __floats2half2_rn(fmaxf(p1.z - q1.z, 0.f), fmaxf(p1.w - q1.w, 0.f));
    __half2 h4 = __floats2half2_rn(fmaxf(p2.x - q2.x, 0.f), fmaxf(p2.y - q2.y, 0.f));
    __half2 h5 = __floats2half2_rn(fmaxf(p2.z - q2.z, 0.f), fmaxf(p2.w - q2.w, 0.f));
    __half2 h6 = __floats2half2_rn(fmaxf(p3.x - q3.x, 0.f), fmaxf(p3.y - q3.y, 0.f));
    __half2 h7 = __floats2half2_rn(fmaxf(p3.z - q3.z, 0.f), fmaxf(p3.w - q3.w, 0.f));
    uint4 w0, w1;
    w0.x = *reinterpret_cast<uint32_t*>(&h0);
    w0.y = *reinterpret_cast<uint32_t*>(&h1);
    w0.z = *reinterpret_cast<uint32_t*>(&h2);
    w0.w = *reinterpret_cast<uint32_t*>(&h3);
    w1.x = *reinterpret_cast<uint32_t*>(&h4);
    w1.y = *reinterpret_cast<uint32_t*>(&h5);
    w1.z = *reinterpret_cast<uint32_t*>(&h6);
    w1.w = *reinterpret_cast<uint32_t*>(&h7);
    const uint32_t zx = (uint32_t)((bj & 7) << 4);
    char* zr = zbuf + (il * 64 + bj) * 128;
    *(uint4*)(zr + (((uint32_t)(qt * 32)) ^ zx))      = w0;
    *(uint4*)(zr + (((uint32_t)(qt * 32 + 16)) ^ zx)) = w1;
}

// ---------------- main: 2-CTA/SM mma GEMM2 + max-pool ----------------
__global__ __launch_bounds__(256, 2) void mainK(float* __restrict__ out) {
    extern __shared__ char smem[];
    float* q_s = (float*)(smem + SM_Q);
    char*  z_c = smem + SM_Z;

    const int tid  = threadIdx.x;
    const int lane = tid & 31;
    const int wid  = tid >> 5;
    const int wn   = wid >> 1;   // i_local 0..3
    const int wd   = wid & 1;    // d-half 0..1 (32 d's each)
    const int bj   = tid >> 2;   // build: j row
    const int qt   = tid & 3;    // build: 16-k quarter

    const uint32_t w_u = smem_u32(smem + SM_W);
    const uint32_t z_u = smem_u32(smem + SM_Z);

    // ---- ldmatrix address precompute ----
    uint32_t arow[2];
#pragma unroll
    for (int mt = 0; mt < 2; mt++) {
        int d = wd * 32 + mt * 16 + (lane & 15);
        arow[mt] = w_u + d * 1024;
    }
    const uint32_t axor  = (uint32_t)((lane & 7) << 4);
    const uint32_t akoff = (uint32_t)((lane >> 4) << 4);
    const int nbase = wn * 64 + (lane & 7) + ((lane & 16) ? 8 : 0);
    const uint32_t brow = z_u + nbase * 128;
    const uint32_t bxor  = axor;
    const uint32_t bkoff = (uint32_t)((lane & 8) << 1);

    const int lo = (int)(((unsigned)blockIdx.x * NITEMS) / gridDim.x);
    const int hi = (int)(((unsigned)(blockIdx.x + 1) * NITEMS) / gridDim.x);

    float s2r[4], c2r[4];
    int prev_dc = -1;

    for (int it = lo; it < hi; it++) {
        const int dc  = it >> 7;       // 0..15
        const int f   = (it >> 2) & 31;
        const int igq = it & 3;

        if (dc != prev_dc) {
            __syncthreads();   // everyone done with old W
            const uint4* src = (const uint4*)(g_Wh + (size_t)dc * 32768);
            uint4* dst = (uint4*)(smem + SM_W);
#pragma unroll
            for (int r = 0; r < 16; r++) dst[tid + r * 256] = src[tid + r * 256];
            __syncthreads();
#pragma unroll
            for (int mt = 0; mt < 2; mt++)
#pragma unroll
                for (int dr = 0; dr < 2; dr++) {
                    int dgl = dc * 64 + wd * 32 + mt * 16 + (lane >> 2) + 8 * dr;
                    s2r[mt * 2 + dr] = g_s2[dgl];
                    c2r[mt * 2 + dr] = g_c2[dgl];
                }
            prev_dc = dc;
        }

        const float* prow_q = g_p + (size_t)(f * 64 + bj) * 512 + qt * 16;

        for (int ig = igq * 4; ig < igq * 4 + 4; ig++) {
            // ---- stage q[4][512] for this i-group ----
#pragma unroll
            for (int r = 0; r < 2; r++) {
                int idx = tid + r * 256;
                int il = idx >> 7, k4 = idx & 127;
                float4 v = *(const float4*)&g_q[(size_t)(f * 64 + ig * 4 + il) * 512 + k4 * 4];
                *(float4*)&q_s[il * 512 + k4 * 4] = v;
            }

            float acc[2][8][4];
#pragma unroll
            for (int mt = 0; mt < 2; mt++)
#pragma unroll
                for (int nt = 0; nt < 8; nt++)
#pragma unroll
                    for (int e = 0; e < 4; e++) acc[mt][nt][e] = 0.f;

            for (int kc = 0; kc < 8; kc++) {
                // prefetch this chunk's p (hides LDG under the barrier)
                float4 pv[4];
                {
                    const float4* psrc = (const float4*)(prow_q + kc * 64);
#pragma unroll
                    for (int r = 0; r < 4; r++) pv[r] = psrc[r];
                }
                __syncthreads();   // z free (prev mma done); q_s visible
#pragma unroll
                for (int il = 0; il < 4; il++)
                    build_quarter(z_c, q_s, pv, kc, il, bj, qt);
                __syncthreads();   // z built

                // ---- mma(kc): C[64d x 256n] += W_chunk^T z_chunk ----
#pragma unroll
                for (int k16 = 0; k16 < 4; k16++) {
                    const uint32_t kbyteA = (uint32_t)(kc * 128 + k16 * 32);
                    uint32_t a[2][4];
#pragma unroll
                    for (int mt = 0; mt < 2; mt++)
                        ldsm4(a[mt], arow[mt] + ((kbyteA + akoff) ^ axor));
                    const uint32_t kbyteB = (uint32_t)(k16 * 32);
#pragma unroll
                    for (int ntp = 0; ntp < 4; ntp++) {
                        uint32_t bb[4];
                        ldsm4(bb, brow + ntp * 2048 + ((kbyteB + bkoff) ^ bxor));
#pragma unroll
                        for (int mt = 0; mt < 2; mt++) {
                            mma16816(acc[mt][2 * ntp],     a[mt], bb[0], bb[1]);
                            mma16816(acc[mt][2 * ntp + 1], a[mt], bb[2], bb[3]);
                        }
                    }
                }
            }

            // ---- epilogue: affine -> max over 64 j -> relu -> store ----
#pragma unroll
            for (int mt = 0; mt < 2; mt++)
#pragma unroll
                for (int dr = 0; dr < 2; dr++) {
                    float s = s2r[mt * 2 + dr], cb = c2r[mt * 2 + dr];
                    float m = -3.402823466e38f;
#pragma unroll
                    for (int nt = 0; nt < 8; nt++) {
                        m = fmaxf(m, fmaf(s, acc[mt][nt][dr * 2 + 0], cb));
                        m = fmaxf(m, fmaf(s, acc[mt][nt][dr * 2 + 1], cb));
                    }
                    m = fmaxf(m, __shfl_xor_sync(0xffffffffu, m, 1));
                    m = fmaxf(m, __shfl_xor_sync(0xffffffffu, m, 2));
                    if ((lane & 3) == 0) {
                        int dgl = dc * 64 + wd * 32 + mt * 16 + (lane >> 2) + 8 * dr;
                        out[(size_t)(f * 64 + ig * 4 + wn) * D_ + dgl] = fmaxf(m, 0.f);
                    }
                }
        }
    }
}

// ---------------- launch ----------------
extern "C" void kernel_launch(void* const* d_in, const int* in_sizes, int n_in,
                              void* d_out, int out_size) {
    const float* h     = (const float*)d_in[0];
    const float* pos   = (const float*)d_in[1];
    const float* We    = (const float*)d_in[3];
    const float* be    = (const float*)d_in[4];
    const float* W1    = (const float*)d_in[5];
    const float* b1    = (const float*)d_in[6];
    const float* g1    = (const float*)d_in[7];
    const float* beta1 = (const float*)d_in[8];
    const float* W2    = (const float*)d_in[9];
    const float* b2    = (const float*)d_in[10];
    const float* g2    = (const float*)d_in[11];
    const float* beta2 = (const float*)d_in[12];
    const float* rm1   = (const float*)d_in[13];
    const float* rv1   = (const float*)d_in[14];
    const float* rm2   = (const float*)d_in[15];
    const float* rv2   = (const float*)d_in[16];
    float* out = (float*)d_out;

    prep0<<<1, 512>>>(We, be, W1, g1, beta1, rm1, rv1, b2, g2, beta2, rm2, rv2);
    prep1<<<B_ / 8, 256>>>(h, pos, W1, b1);
    prep2<<<dim3(16, 8), 256>>>(W2);
    cudaFuncSetAttribute(mainK, cudaFuncAttributeMaxDynamicSharedMemorySize, SM_TOTAL);
    mainK<<<296, 256, SM_TOTAL>>>(out);
}

// round 15
// speedup vs baseline: 1.3713x; 1.3713x over previous
#include <cuda_runtime.h>
#include <cuda_fp16.h>
#include <cstdint>

// ---------------- shapes ----------------
#define B_   2048
#define F_   32
#define P_   64
#define E_   64
#define H_   128
#define M_   512      // K of GEMM2
#define D_   1024
#define EPSV 1e-5f

// ---------------- device scratch ----------------
__device__ float g_C0[M_], g_C1[M_], g_v[M_], g_s1[M_], g_c1[M_];
__device__ float g_s2[D_], g_c2[D_];
__device__ float g_p[B_ * M_];
__device__ float g_q[B_ * M_];
// W2^T fp16: [dc(8)][d(128)][k(512) ^ ((d&7)<<3)]  (XOR-swizzled rows of 1KB)
__device__ __half g_Wh[8 * 128 * 512];

// ---------------- SMEM layout (bytes, dynamic) ----------------
#define SM_Q     0        // q_s[4][512] f32 = 8192
#define SM_W     8192     // W tile fp16 128x512 swizzled = 131072
#define SM_Z0    139264   // z buf 0: 256n x 64k fp16 = 32768
#define SM_Z1    172032   // z buf 1
#define SM_TOTAL 204800

#define NITEMS 1024       // (dc 8) x (f 32) x (igq 4)

__device__ __forceinline__ uint32_t smem_u32(const void* p) {
    uint32_t a;
    asm("{ .reg .u64 t; cvta.to.shared.u64 t, %1; cvt.u32.u64 %0, t; }" : "=r"(a) : "l"(p));
    return a;
}
__device__ __forceinline__ void ldsm4(uint32_t* r, uint32_t addr) {
    asm volatile("ldmatrix.sync.aligned.m8n8.x4.shared.b16 {%0,%1,%2,%3}, [%4];"
                 : "=r"(r[0]), "=r"(r[1]), "=r"(r[2]), "=r"(r[3]) : "r"(addr));
}
__device__ __forceinline__ void mma16816(float* c, const uint32_t* a,
                                         uint32_t b0, uint32_t b1) {
    asm volatile(
        "mma.sync.aligned.m16n8k16.row.col.f32.f16.f16.f32 "
        "{%0,%1,%2,%3}, {%4,%5,%6,%7}, {%8,%9}, {%0,%1,%2,%3};"
        : "+f"(c[0]), "+f"(c[1]), "+f"(c[2]), "+f"(c[3])
        : "r"(a[0]), "r"(a[1]), "r"(a[2]), "r"(a[3]), "r"(b0), "r"(b1));
}

// ---------------- prep0: fold constants ----------------
__global__ void prep0(const float* __restrict__ We, const float* __restrict__ be,
                      const float* __restrict__ W1,
                      const float* __restrict__ g1, const float* __restrict__ beta1,
                      const float* __restrict__ rm1, const float* __restrict__ rv1,
                      const float* __restrict__ b2, const float* __restrict__ g2,
                      const float* __restrict__ beta2,
                      const float* __restrict__ rm2, const float* __restrict__ rv2) {
    int m = threadIdx.x;  // 512
    float c0 = 0.f, c1 = 0.f, vv = 0.f;
#pragma unroll 8
    for (int e = 0; e < E_; e++) {
        float w = W1[e * M_ + m];
        c0 += We[e] * w;
        c1 += We[E_ + e] * w;
        vv += be[e] * w;
    }
    g_C0[m] = c0;
    g_C1[m] = c1;
    g_v[m]  = vv;
    float s = g1[m] * rsqrtf(rv1[m] + EPSV);
    g_s1[m] = s;
    g_c1[m] = beta1[m] - s * rm1[m];
    for (int d = m; d < D_; d += M_) {
        float s2 = g2[d] * rsqrtf(rv2[d] + EPSV);
        g_s2[d] = s2;
        g_c2[d] = beta2[d] + s2 * (b2[d] - rm2[d]);
    }
}

// ---------------- prep1: build p,q ----------------
__global__ void prep1(const float* __restrict__ h, const float* __restrict__ pos,
                      const float* __restrict__ W1, const float* __restrict__ b1) {
    __shared__ float hs[8][H_];
    __shared__ float ps[8][2];
    int tid = threadIdx.x;
    int b0 = blockIdx.x * 8;
    for (int idx = tid; idx < 8 * H_; idx += 256) {
        int bb = idx >> 7, k = idx & 127;
        hs[bb][k] = h[(b0 + bb) * H_ + k];
    }
    if (tid < 16) ps[tid >> 1][tid & 1] = pos[b0 * 2 + tid];
    __syncthreads();

    int m0 = tid * 2;
    float acc[8][2];
#pragma unroll
    for (int bb = 0; bb < 8; bb++) { acc[bb][0] = 0.f; acc[bb][1] = 0.f; }
#pragma unroll 4
    for (int k = 0; k < H_; k++) {
        float2 w = *(const float2*)&W1[(E_ + k) * M_ + m0];
#pragma unroll
        for (int bb = 0; bb < 8; bb++) {
            float hv = hs[bb][k];
            acc[bb][0] += hv * w.x;
            acc[bb][1] += hv * w.y;
        }
    }
#pragma unroll
    for (int mm = 0; mm < 2; mm++) {
        int m = m0 + mm;
        float C0 = g_C0[m], C1 = g_C1[m], vv = g_v[m];
        float s = g_s1[m], cc = g_c1[m], bb1 = b1[m];
#pragma unroll
        for (int bb = 0; bb < 8; bb++) {
            float u = ps[bb][0] * C0 + ps[bb][1] * C1;
            float a = u + acc[bb][mm] + vv + bb1;
            g_p[(b0 + bb) * M_ + m] = s * a + cc;
            g_q[(b0 + bb) * M_ + m] = s * u;
        }
    }
}

// ---------------- prep2: W2^T -> fp16 swizzled ----------------
__global__ void prep2(const float* __restrict__ W2) {
    int dc = blockIdx.x;   // 0..7
    int ks = blockIdx.y;   // 0..7 (k-slab of 64)
    for (int idx = threadIdx.x; idx < 8192; idx += 256) {
        int d = idx & 127;                 // coalesced over d
        int k = ks * 64 + (idx >> 7);
        float w = W2[(size_t)k * D_ + dc * 128 + d];
        int kk = k ^ ((d & 7) << 3);
        g_Wh[dc * 65536 + d * 512 + kk] = __float2half_rn(w);
    }
}

// ---------------- build one il-quarter of a z chunk ----------------
// thread map: bj = tid>>2 (j row), qt = tid&3 (16-k quarter).
__device__ __forceinline__ void build_quarter(char* zbuf, const float* q_s,
                                              const float4* pv, int kc, int il,
                                              int bj, int qt) {
    const float4* qq = (const float4*)(q_s + il * 512 + kc * 64 + qt * 16);
    float4 q0 = qq[0], q1 = qq[1], q2 = qq[2], q3 = qq[3];
    float4 p0 = pv[0], p1 = pv[1], p2 = pv[2], p3 = pv[3];
    __half2 h0 = __floats2half2_rn(fmaxf(p0.x - q0.x, 0.f), fmaxf(p0.y - q0.y, 0.f));
    __half2 h1 = __floats2half2_rn(fmaxf(p0.z - q0.z, 0.f), fmaxf(p0.w - q0.w, 0.f));
    __half2 h2 = __floats2half2_rn(fmaxf(p1.x - q1.x, 0.f), fmaxf(p1.y - q1.y, 0.f));
    __half2 h3 = __floats2half2_rn(fmaxf(p1.z - q1.z, 0.f), fmaxf(p1.w - q1.w, 0.f));
    __half2 h4 = __floats2half2_rn(fmaxf(p2.x - q2.x, 0.f), fmaxf(p2.y - q2.y, 0.f));
    __half2 h5 = __floats2half2_rn(fmaxf(p2.z - q2.z, 0.f), fmaxf(p2.w - q2.w, 0.f));
    __half2 h6 = __floats2half2_rn(fmaxf(p3.x - q3.x, 0.f), fmaxf(p3.y - q3.y, 0.f));
    __half2 h7 = __floats2half2_rn(fmaxf(p3.z - q3.z, 0.f), fmaxf(p3.w - q3.w, 0.f));
    uint4 w0, w1;
    w0.x = *reinterpret_cast<uint32_t*>(&h0);
    w0.y = *reinterpret_cast<uint32_t*>(&h1);
    w0.z = *reinterpret_cast<uint32_t*>(&h2);
    w0.w = *reinterpret_cast<uint32_t*>(&h3);
    w1.x = *reinterpret_cast<uint32_t*>(&h4);
    w1.y = *reinterpret_cast<uint32_t*>(&h5);
    w1.z = *reinterpret_cast<uint32_t*>(&h6);
    w1.w = *reinterpret_cast<uint32_t*>(&h7);
    const uint32_t zx = (uint32_t)((bj & 7) << 4);
    char* zr = zbuf + (il * 64 + bj) * 128;
    *(uint4*)(zr + (((uint32_t)(qt * 32)) ^ zx))      = w0;
    *(uint4*)(zr + (((uint32_t)(qt * 32 + 16)) ^ zx)) = w1;
}

// ---------------- main: long-region pipelined mma GEMM2 + max-pool ----------------
__global__ __launch_bounds__(256, 1) void mainK(float* __restrict__ out) {
    extern __shared__ char smem[];
    float* q_s = (float*)(smem + SM_Q);
    char* zb[2] = {smem + SM_Z0, smem + SM_Z1};

    const int tid  = threadIdx.x;
    const int lane = tid & 31;
    const int wid  = tid >> 5;
    const int wn   = wid >> 1;   // i_local 0..3
    const int wd   = wid & 1;    // d-half 0..1
    const int bj   = tid >> 2;   // build: j row
    const int qt   = tid & 3;    // build: 16-k quarter

    const uint32_t w_u  = smem_u32(smem + SM_W);
    const uint32_t z_u0 = smem_u32(smem + SM_Z0);
    const uint32_t z_u1 = smem_u32(smem + SM_Z1);

    // ---- ldmatrix address precompute ----
    uint32_t arow[4];
#pragma unroll
    for (int mt = 0; mt < 4; mt++) {
        int d = wd * 64 + mt * 16 + (lane & 15);
        arow[mt] = w_u + d * 1024;
    }
    const uint32_t axor  = (uint32_t)((lane & 7) << 4);
    const uint32_t akoff = (uint32_t)((lane >> 4) << 4);
    const int nbase = wn * 64 + (lane & 7) + ((lane & 16) ? 8 : 0);
    const uint32_t brow0 = z_u0 + nbase * 128;
    const uint32_t brow1 = z_u1 + nbase * 128;
    const uint32_t bxor  = axor;
    const uint32_t bkoff = (uint32_t)((lane & 8) << 1);

    const int lo = (int)(((unsigned)blockIdx.x * NITEMS) / gridDim.x);
    const int hi = (int)(((unsigned)(blockIdx.x + 1) * NITEMS) / gridDim.x);

    float s2r[8], c2r[8];
    int prev_dc = -1;

    for (int it = lo; it < hi; it++) {
        const int dc  = it >> 7;
        const int f   = (it >> 2) & 31;
        const int igq = it & 3;

        if (dc != prev_dc) {
            __syncthreads();   // everyone done with old W
            const uint4* src = (const uint4*)(g_Wh + (size_t)dc * 65536);
            uint4* dst = (uint4*)(smem + SM_W);
#pragma unroll
            for (int r = 0; r < 32; r++) dst[tid + r * 256] = src[tid + r * 256];
            __syncthreads();
#pragma unroll
            for (int mt = 0; mt < 4; mt++)
#pragma unroll
                for (int dr = 0; dr < 2; dr++) {
                    int dgl = dc * 128 + wd * 64 + mt * 16 + (lane >> 2) + 8 * dr;
                    s2r[mt * 2 + dr] = g_s2[dgl];
                    c2r[mt * 2 + dr] = g_c2[dgl];
                }
            prev_dc = dc;
        }

        const float* prow_q = g_p + (size_t)(f * 64 + bj) * 512 + qt * 16;

        for (int ig = igq * 4; ig < igq * 4 + 4; ig++) {
            // ---- prefetch p for chunk pair 0 (overlaps q staging) ----
            float4 pv[8];
#pragma unroll
            for (int s = 0; s < 2; s++) {
                const float4* psrc = (const float4*)(prow_q + s * 64);
#pragma unroll
                for (int r = 0; r < 4; r++) pv[s * 4 + r] = psrc[r];
            }

            // ---- stage q[4][512] for this i-group ----
#pragma unroll
            for (int r = 0; r < 2; r++) {
                int idx = tid + r * 256;
                int il = idx >> 7, k4 = idx & 127;
                float4 v = *(const float4*)&g_q[(size_t)(f * 64 + ig * 4 + il) * 512 + k4 * 4];
                *(float4*)&q_s[il * 512 + k4 * 4] = v;
            }
            __syncthreads();   // q ready; prev ig fully done (z free)

            float acc[4][8][4];
#pragma unroll
            for (int mt = 0; mt < 4; mt++)
#pragma unroll
                for (int nt = 0; nt < 8; nt++)
#pragma unroll
                    for (int e = 0; e < 4; e++) acc[mt][nt][e] = 0.f;

            for (int kc2 = 0; kc2 < 4; kc2++) {
                // ---- build phase: both chunks of the pair ----
#pragma unroll
                for (int s = 0; s < 2; s++) {
                    const int kcc = kc2 * 2 + s;
#pragma unroll
                    for (int il = 0; il < 4; il++)
                        build_quarter(zb[s], q_s, pv + s * 4, kcc, il, bj, qt);
                }
                __syncthreads();   // z pair built

                // ---- prefetch next pair's p (latency hides under mma) ----
                if (kc2 < 3) {
#pragma unroll
                    for (int s = 0; s < 2; s++) {
                        const float4* psrc = (const float4*)(prow_q + (kc2 * 2 + 2 + s) * 64);
#pragma unroll
                        for (int r = 0; r < 4; r++) pv[s * 4 + r] = psrc[r];
                    }
                }

                // ---- mma phase: 128 k over both buffers ----
#pragma unroll
                for (int s = 0; s < 2; s++) {
                    const int kcc = kc2 * 2 + s;
                    const uint32_t brow = s ? brow1 : brow0;
#pragma unroll
                    for (int k16 = 0; k16 < 4; k16++) {
                        const uint32_t kbyteA = (uint32_t)(kcc * 128 + k16 * 32);
                        uint32_t a[4][4];
#pragma unroll
                        for (int mt = 0; mt < 4; mt++)
                            ldsm4(a[mt], arow[mt] + ((kbyteA + akoff) ^ axor));
                        const uint32_t kbyteB = (uint32_t)(k16 * 32);
#pragma unroll
                        for (int ntp = 0; ntp < 4; ntp++) {
                            uint32_t bb[4];
                            ldsm4(bb, brow + ntp * 2048 + ((kbyteB + bkoff) ^ bxor));
#pragma unroll
                            for (int mt = 0; mt < 4; mt++) {
                                mma16816(acc[mt][2 * ntp],     a[mt], bb[0], bb[1]);
                                mma16816(acc[mt][2 * ntp + 1], a[mt], bb[2], bb[3]);
                            }
                        }
                    }
                }
                __syncthreads();   // all z reads done -> buffers reusable
            }

            // ---- epilogue: affine -> max over 64 j -> relu -> store ----
#pragma unroll
            for (int mt = 0; mt < 4; mt++)
#pragma unroll
                for (int dr = 0; dr < 2; dr++) {
                    float s = s2r[mt * 2 + dr], cb = c2r[mt * 2 + dr];
                    float m = -3.402823466e38f;
#pragma unroll
                    for (int nt = 0; nt < 8; nt++) {
                        m = fmaxf(m, fmaf(s, acc[mt][nt][dr * 2 + 0], cb));
                        m = fmaxf(m, fmaf(s, acc[mt][nt][dr * 2 + 1], cb));
                    }
                    m = fmaxf(m, __shfl_xor_sync(0xffffffffu, m, 1));
                    m = fmaxf(m, __shfl_xor_sync(0xffffffffu, m, 2));
                    if ((lane & 3) == 0) {
                        int dgl = dc * 128 + wd * 64 + mt * 16 + (lane >> 2) + 8 * dr;
                        out[(size_t)(f * 64 + ig * 4 + wn) * D_ + dgl] = fmaxf(m, 0.f);
                    }
                }
        }
    }
}

// ---------------- launch ----------------
extern "C" void kernel_launch(void* const* d_in, const int* in_sizes, int n_in,
                              void* d_out, int out_size) {
    const float* h     = (const float*)d_in[0];
    const float* pos   = (const float*)d_in[1];
    const float* We    = (const float*)d_in[3];
    const float* be    = (const float*)d_in[4];
    const float* W1    = (const float*)d_in[5];
    const float* b1    = (const float*)d_in[6];
    const float* g1    = (const float*)d_in[7];
    const float* beta1 = (const float*)d_in[8];
    const float* W2    = (const float*)d_in[9];
    const float* b2    = (const float*)d_in[10];
    const float* g2    = (const float*)d_in[11];
    const float* beta2 = (const float*)d_in[12];
    const float* rm1   = (const float*)d_in[13];
    const float* rv1   = (const float*)d_in[14];
    const float* rm2   = (const float*)d_in[15];
    const float* rv2   = (const float*)d_in[16];
    float* out = (float*)d_out;

    prep0<<<1, 512>>>(We, be, W1, g1, beta1, rm1, rv1, b2, g2, beta2, rm2, rv2);
    prep1<<<B_ / 8, 256>>>(h, pos, W1, b1);
    prep2<<<dim3(8, 8), 256>>>(W2);
    cudaFuncSetAttribute(mainK, cudaFuncAttributeMaxDynamicSharedMemorySize, SM_TOTAL);
    mainK<<<148, 256, SM_TOTAL>>>(out);
}